// round 2
// baseline (speedup 1.0000x reference)
#include <cuda_runtime.h>

#define Nn   50000
#define Ee   800000
#define FIN  128
#define HID  128
#define OUTC 64
#define NEXP 3
#define NG   64
#define TEMP_INV (1.0f/101.0f)

// ---------------- scratch (device globals; no allocations) ----------------
static __device__ int    g_deg[Nn];
static __device__ float  g_dinv[Nn];
static __device__ int    g_rowptr[Nn + 1];
static __device__ int    g_cursor[Nn];
static __device__ int    g_col[Ee];
static __device__ float  g_cw[Ee];       // dinv[src] per CSR entry
static __device__ float  g_gate0[Nn * 3];
static __device__ float  g_gate1[Nn * 3];
static __device__ float  g_bufA[Nn * HID];   // aggregation output
static __device__ float  g_bufB[Nn * HID];   // layer output
static __device__ float  g_sums[NG * HID];
static __device__ float  g_cnt[NG];
static __device__ int    g_tmpScan[Nn];
static __device__ int    g_blockSums[128];
static __device__ int    g_blockOffs[128];

// ---------------- small prep kernels ----------------
__global__ void k_zero() {
    int i = blockIdx.x * blockDim.x + threadIdx.x;
    if (i < Nn) { g_deg[i] = 0; g_cursor[i] = 0; }
    if (i < NG * HID) g_sums[i] = 0.f;
    if (i < NG) g_cnt[i] = 0.f;
}

__global__ void k_hist(const int* __restrict__ ei) {
    int i = blockIdx.x * blockDim.x + threadIdx.x;
    if (i < Ee) atomicAdd(&g_deg[ei[Ee + i]], 1);
}

// dinv + both gate softmaxes
__global__ void k_prep(const float* __restrict__ top,
                       const float* __restrict__ Wg0,
                       const float* __restrict__ Wg1) {
    int n = blockIdx.x * blockDim.x + threadIdx.x;
    if (n >= Nn) return;
    g_dinv[n] = rsqrtf((float)(g_deg[n] + 1));

    float t0 = top[n * 4 + 0], t1 = top[n * 4 + 1];
    float t2 = top[n * 4 + 2], t3 = top[n * 4 + 3];

    #pragma unroll
    for (int L = 0; L < 2; L++) {
        const float* Wg = L ? Wg1 : Wg0;
        float* gate = L ? g_gate1 : g_gate0;
        float l[3];
        #pragma unroll
        for (int e = 0; e < 3; e++)
            l[e] = (t0 * Wg[e * 4 + 0] + t1 * Wg[e * 4 + 1] +
                    t2 * Wg[e * 4 + 2] + t3 * Wg[e * 4 + 3]) * TEMP_INV;
        float mx = fmaxf(l[0], fmaxf(l[1], l[2]));
        float e0 = expf(l[0] - mx), e1 = expf(l[1] - mx), e2 = expf(l[2] - mx);
        float inv = 1.0f / (e0 + e1 + e2);
        gate[n * 3 + 0] = e0 * inv;
        gate[n * 3 + 1] = e1 * inv;
        gate[n * 3 + 2] = e2 * inv;
    }
}

// ---------------- scan (row_ptr = exclusive cumsum of deg) ----------------
__global__ void k_scan1() {  // grid = 98, block = 512
    __shared__ int s[512];
    int i = blockIdx.x * 512 + threadIdx.x;
    int v = (i < Nn) ? g_deg[i] : 0;
    s[threadIdx.x] = v;
    __syncthreads();
    for (int off = 1; off < 512; off <<= 1) {
        int t = (threadIdx.x >= off) ? s[threadIdx.x - off] : 0;
        __syncthreads();
        s[threadIdx.x] += t;
        __syncthreads();
    }
    if (i < Nn) g_tmpScan[i] = s[threadIdx.x];
    if (threadIdx.x == 511) g_blockSums[blockIdx.x] = s[511];
}

__global__ void k_scan2() {  // 1 block of 128
    __shared__ int s[128];
    int t = threadIdx.x;
    int v = (t < 98) ? g_blockSums[t] : 0;
    s[t] = v;
    __syncthreads();
    for (int off = 1; off < 128; off <<= 1) {
        int u = (t >= off) ? s[t - off] : 0;
        __syncthreads();
        s[t] += u;
        __syncthreads();
    }
    if (t < 98) g_blockOffs[t] = s[t] - v;   // exclusive
}

__global__ void k_scan3() {
    int i = blockIdx.x * blockDim.x + threadIdx.x;
    if (i == 0) g_rowptr[0] = 0;
    if (i < Nn) g_rowptr[i + 1] = g_tmpScan[i] + g_blockOffs[i >> 9];
}

__global__ void k_fill(const int* __restrict__ ei) {
    int i = blockIdx.x * blockDim.x + threadIdx.x;
    if (i >= Ee) return;
    int s = ei[i];
    int d = ei[Ee + i];
    int p = g_rowptr[d] + atomicAdd(&g_cursor[d], 1);
    g_col[p] = s;
    g_cw[p] = g_dinv[s];
}

// ---------------- CSR aggregation: bufA[d] = sum_{s in N(d)} norm * h[s] ----------------
__global__ void __launch_bounds__(256) k_agg(const float* __restrict__ xin, int useBuf) {
    const float* h = useBuf ? g_bufB : xin;
    int w = (blockIdx.x * 256 + threadIdx.x) >> 5;   // node = warp id
    int lane = threadIdx.x & 31;
    if (w >= Nn) return;

    float dd = g_dinv[w];
    const float4* h4 = (const float4*)h;
    // self-loop: norm = dinv[d]^2
    float4 v = h4[w * 32 + lane];
    float s2 = dd * dd;
    float4 acc = make_float4(v.x * s2, v.y * s2, v.z * s2, v.w * s2);

    int j0 = g_rowptr[w], j1 = g_rowptr[w + 1];
    for (int j = j0; j < j1; j++) {
        int s = __ldg(&g_col[j]);
        float wt = dd * __ldg(&g_cw[j]);
        float4 u = h4[s * 32 + lane];
        acc.x += wt * u.x; acc.y += wt * u.y;
        acc.z += wt * u.z; acc.w += wt * u.w;
    }
    ((float4*)g_bufA)[w * 32 + lane] = acc;
}

// ---------------- fused MoE GEMM: bufB = sum_e gate_e * relu(bufA @ W_e + b_e) ----------------
// tile: 64 rows x 64 cols, 256 threads, thread computes 4x4; loops experts.
__global__ void __launch_bounds__(256) k_moegemm(const float* __restrict__ W,
                                                 const float* __restrict__ bias,
                                                 int layer) {
    extern __shared__ float sm[];
    float* As = sm;                 // [64][132]
    float* Bs = sm + 64 * 132;      // [128][68]
    float* Gs = Bs + 128 * 68;      // [64][4]

    const float* gate = layer ? g_gate1 : g_gate0;
    const int tid = threadIdx.x;
    const int tx = tid & 15, ty = tid >> 4;
    const int baseM = blockIdx.x * 64;
    const int baseN = blockIdx.y * 64;

    // load A tile (64 x 128), natural layout, coalesced
    #pragma unroll
    for (int t = 0; t < 8; t++) {
        int idx = tid + t * 256;      // 0..2047
        int m = idx >> 5, k4 = idx & 31;
        float4 v = make_float4(0.f, 0.f, 0.f, 0.f);
        int row = baseM + m;
        if (row < Nn) v = ((const float4*)g_bufA)[row * 32 + k4];
        *(float4*)&As[m * 132 + k4 * 4] = v;
    }
    if (tid < 64) {
        int row = baseM + tid;
        float g0 = 0.f, g1 = 0.f, g2 = 0.f;
        if (row < Nn) {
            g0 = gate[row * 3 + 0];
            g1 = gate[row * 3 + 1];
            g2 = gate[row * 3 + 2];
        }
        Gs[tid * 4 + 0] = g0; Gs[tid * 4 + 1] = g1; Gs[tid * 4 + 2] = g2;
    }

    float outAcc[4][4];
    #pragma unroll
    for (int i = 0; i < 4; i++)
        #pragma unroll
        for (int j = 0; j < 4; j++) outAcc[i][j] = 0.f;

    #pragma unroll 1
    for (int e = 0; e < NEXP; e++) {
        __syncthreads();   // covers As/Gs readiness (e=0) and Bs reuse (e>0)
        #pragma unroll
        for (int t = 0; t < 8; t++) {
            int idx = tid + t * 256;  // 0..2047
            int k = idx >> 4, n4 = idx & 15;
            float4 v = ((const float4*)W)[e * (128 * 32) + k * 32 + (baseN >> 2) + n4];
            *(float4*)&Bs[k * 68 + n4 * 4] = v;
        }
        __syncthreads();

        float acc[4][4];
        #pragma unroll
        for (int i = 0; i < 4; i++)
            #pragma unroll
            for (int j = 0; j < 4; j++) acc[i][j] = 0.f;

        #pragma unroll 8
        for (int k = 0; k < 128; k++) {
            float4 b4 = *(const float4*)&Bs[k * 68 + tx * 4];
            float a0 = As[(ty     ) * 132 + k];
            float a1 = As[(ty + 16) * 132 + k];
            float a2 = As[(ty + 32) * 132 + k];
            float a3 = As[(ty + 48) * 132 + k];
            acc[0][0] += a0 * b4.x; acc[0][1] += a0 * b4.y; acc[0][2] += a0 * b4.z; acc[0][3] += a0 * b4.w;
            acc[1][0] += a1 * b4.x; acc[1][1] += a1 * b4.y; acc[1][2] += a1 * b4.z; acc[1][3] += a1 * b4.w;
            acc[2][0] += a2 * b4.x; acc[2][1] += a2 * b4.y; acc[2][2] += a2 * b4.z; acc[2][3] += a2 * b4.w;
            acc[3][0] += a3 * b4.x; acc[3][1] += a3 * b4.y; acc[3][2] += a3 * b4.z; acc[3][3] += a3 * b4.w;
        }

        float4 bb = ((const float4*)bias)[e * 32 + (baseN >> 2) + tx];
        #pragma unroll
        for (int i = 0; i < 4; i++) {
            float g = Gs[(ty + 16 * i) * 4 + e];
            outAcc[i][0] += g * fmaxf(acc[i][0] + bb.x, 0.f);
            outAcc[i][1] += g * fmaxf(acc[i][1] + bb.y, 0.f);
            outAcc[i][2] += g * fmaxf(acc[i][2] + bb.z, 0.f);
            outAcc[i][3] += g * fmaxf(acc[i][3] + bb.w, 0.f);
        }
    }

    #pragma unroll
    for (int i = 0; i < 4; i++) {
        int row = baseM + ty + 16 * i;
        if (row < Nn)
            ((float4*)g_bufB)[row * 32 + (baseN >> 2) + tx] =
                make_float4(outAcc[i][0], outAcc[i][1], outAcc[i][2], outAcc[i][3]);
    }
}

// ---------------- pooling + final linear ----------------
__global__ void k_pool(const int* __restrict__ batch) {
    int idx = blockIdx.x * blockDim.x + threadIdx.x;
    if (idx >= Nn * 32) return;
    int n = idx >> 5, c = idx & 31;
    int g = batch[n];
    float4 v = ((const float4*)g_bufB)[n * 32 + c];
    atomicAdd(&g_sums[g * 128 + c * 4 + 0], v.x);
    atomicAdd(&g_sums[g * 128 + c * 4 + 1], v.y);
    atomicAdd(&g_sums[g * 128 + c * 4 + 2], v.z);
    atomicAdd(&g_sums[g * 128 + c * 4 + 3], v.w);
    if (c == 0) atomicAdd(&g_cnt[g], 1.0f);
}

__global__ void k_final(const float* __restrict__ Wf,
                        const float* __restrict__ bf,
                        float* __restrict__ out) {
    __shared__ float p[128];
    int g = blockIdx.x;
    float inv = 1.0f / fmaxf(g_cnt[g], 1.0f);
    if (threadIdx.x < 128) p[threadIdx.x] = g_sums[g * 128 + threadIdx.x] * inv;
    __syncthreads();
    if (threadIdx.x < OUTC) {
        float acc = bf[threadIdx.x];
        #pragma unroll 16
        for (int k = 0; k < 128; k++)
            acc += p[k] * Wf[k * OUTC + threadIdx.x];
        out[g * OUTC + threadIdx.x] = acc;
    }
}

// ---------------- launch ----------------
extern "C" void kernel_launch(void* const* d_in, const int* in_sizes, int n_in,
                              void* d_out, int out_size) {
    const float* x     = (const float*)d_in[0];
    const float* top   = (const float*)d_in[1];
    const int*   ei    = (const int*)d_in[2];    // JAX x64 disabled -> int32
    const int*   batch = (const int*)d_in[3];    // int32
    const float* W0    = (const float*)d_in[4];
    const float* b0    = (const float*)d_in[5];
    const float* Wg0   = (const float*)d_in[6];
    const float* W1    = (const float*)d_in[7];
    const float* b1    = (const float*)d_in[8];
    const float* Wg1   = (const float*)d_in[9];
    const float* Wf    = (const float*)d_in[10];
    const float* bf    = (const float*)d_in[11];
    float*       out   = (float*)d_out;

    const int SMEM_GEMM = (64 * 132 + 128 * 68 + 64 * 4) * 4;  // 69632 B
    cudaFuncSetAttribute(k_moegemm, cudaFuncAttributeMaxDynamicSharedMemorySize, SMEM_GEMM);

    dim3 gemmGrid((Nn + 63) / 64, 2);

    k_zero<<<(Nn + 255) / 256, 256>>>();
    k_hist<<<(Ee + 255) / 256, 256>>>(ei);
    k_prep<<<(Nn + 255) / 256, 256>>>(top, Wg0, Wg1);
    k_scan1<<<98, 512>>>();
    k_scan2<<<1, 128>>>();
    k_scan3<<<(Nn + 255) / 256, 256>>>();
    k_fill<<<(Ee + 255) / 256, 256>>>(ei);

    // layer 0
    k_agg<<<(Nn * 32 + 255) / 256, 256>>>(x, 0);
    k_moegemm<<<gemmGrid, 256, SMEM_GEMM>>>(W0, b0, 0);
    // layer 1
    k_agg<<<(Nn * 32 + 255) / 256, 256>>>(x, 1);
    k_moegemm<<<gemmGrid, 256, SMEM_GEMM>>>(W1, b1, 1);

    k_pool<<<(Nn * 32 + 255) / 256, 256>>>(batch);
    k_final<<<NG, 128>>>(Wf, bf, out);
}

// round 4
// speedup vs baseline: 1.4740x; 1.4740x over previous
#include <cuda_runtime.h>
#include <cuda_bf16.h>
#include <cstdint>

#define Nn   50000
#define Ee   800000
#define HID  128
#define OUTC 64
#define NG   64
#define TEMP_INV (1.0f/101.0f)

// ---------------- scratch ----------------
static __device__ int    g_deg[Nn];
static __device__ float  g_dinv[Nn];
static __device__ int    g_rowptr[Nn + 1];
static __device__ int    g_cursor[Nn];
static __device__ int    g_col[Ee];
static __device__ float  g_cw[Ee];
static __device__ float  g_gate0[Nn * 3];
static __device__ float  g_gate1[Nn * 3];
static __device__ float  g_bufA[Nn * HID];
static __device__ float  g_bufB[Nn * HID];
static __device__ float  g_sums[NG * HID];
static __device__ float  g_cnt[NG];
static __device__ int    g_tmpScan[Nn];
static __device__ int    g_blockSums[128];
static __device__ int    g_blockOffs[128];
// bf16 split transposed weights: [L][e][n][k], hi and lo
static __device__ __align__(16) __nv_bfloat16 g_Wh[2 * 3 * 128 * 128];
static __device__ __align__(16) __nv_bfloat16 g_Wl[2 * 3 * 128 * 128];

// ---------------- prep kernels ----------------
__global__ void k_zero() {
    int i = blockIdx.x * blockDim.x + threadIdx.x;
    if (i < Nn) { g_deg[i] = 0; g_cursor[i] = 0; }
    if (i < NG * HID) g_sums[i] = 0.f;
    if (i < NG) g_cnt[i] = 0.f;
}

__global__ void k_hist(const int* __restrict__ ei) {
    int i = blockIdx.x * blockDim.x + threadIdx.x;
    if (i < Ee) atomicAdd(&g_deg[ei[Ee + i]], 1);
}

__global__ void k_prep(const float* __restrict__ top,
                       const float* __restrict__ Wg0,
                       const float* __restrict__ Wg1) {
    int n = blockIdx.x * blockDim.x + threadIdx.x;
    if (n >= Nn) return;
    g_dinv[n] = rsqrtf((float)(g_deg[n] + 1));
    float t0 = top[n*4+0], t1 = top[n*4+1], t2 = top[n*4+2], t3 = top[n*4+3];
    #pragma unroll
    for (int L = 0; L < 2; L++) {
        const float* Wg = L ? Wg1 : Wg0;
        float* gate = L ? g_gate1 : g_gate0;
        float l[3];
        #pragma unroll
        for (int e = 0; e < 3; e++)
            l[e] = (t0*Wg[e*4+0] + t1*Wg[e*4+1] + t2*Wg[e*4+2] + t3*Wg[e*4+3]) * TEMP_INV;
        float mx = fmaxf(l[0], fmaxf(l[1], l[2]));
        float e0 = expf(l[0]-mx), e1 = expf(l[1]-mx), e2 = expf(l[2]-mx);
        float inv = 1.0f / (e0 + e1 + e2);
        gate[n*3+0] = e0*inv; gate[n*3+1] = e1*inv; gate[n*3+2] = e2*inv;
    }
}

// transpose + bf16-split expert weights: [L][e][n][k] from W[e][k][n]
__global__ void k_wprep(const float* __restrict__ W0, const float* __restrict__ W1) {
    int idx = blockIdx.x * blockDim.x + threadIdx.x;
    if (idx >= 2 * 3 * 16384) return;
    int L = idx / 49152, rem = idx % 49152;
    int e = rem / 16384, nk = rem % 16384;
    int n = nk >> 7, k = nk & 127;
    const float* W = L ? W1 : W0;
    float w = W[e * 16384 + k * 128 + n];
    __nv_bfloat16 hi = __float2bfloat16_rn(w);
    g_Wh[idx] = hi;
    g_Wl[idx] = __float2bfloat16_rn(w - __bfloat162float(hi));
}

// ---------------- scan ----------------
__global__ void k_scan1() {
    __shared__ int s[512];
    int i = blockIdx.x * 512 + threadIdx.x;
    int v = (i < Nn) ? g_deg[i] : 0;
    s[threadIdx.x] = v; __syncthreads();
    for (int off = 1; off < 512; off <<= 1) {
        int t = (threadIdx.x >= off) ? s[threadIdx.x - off] : 0;
        __syncthreads(); s[threadIdx.x] += t; __syncthreads();
    }
    if (i < Nn) g_tmpScan[i] = s[threadIdx.x];
    if (threadIdx.x == 511) g_blockSums[blockIdx.x] = s[511];
}
__global__ void k_scan2() {
    __shared__ int s[128];
    int t = threadIdx.x;
    int v = (t < 98) ? g_blockSums[t] : 0;
    s[t] = v; __syncthreads();
    for (int off = 1; off < 128; off <<= 1) {
        int u = (t >= off) ? s[t - off] : 0;
        __syncthreads(); s[t] += u; __syncthreads();
    }
    if (t < 98) g_blockOffs[t] = s[t] - v;
}
__global__ void k_scan3() {
    int i = blockIdx.x * blockDim.x + threadIdx.x;
    if (i == 0) g_rowptr[0] = 0;
    if (i < Nn) g_rowptr[i + 1] = g_tmpScan[i] + g_blockOffs[i >> 9];
}
__global__ void k_fill(const int* __restrict__ ei) {
    int i = blockIdx.x * blockDim.x + threadIdx.x;
    if (i >= Ee) return;
    int s = ei[i], d = ei[Ee + i];
    int p = g_rowptr[d] + atomicAdd(&g_cursor[d], 1);
    g_col[p] = s;
    g_cw[p] = g_dinv[s];
}

// ---------------- CSR aggregation ----------------
__global__ void __launch_bounds__(256) k_agg(const float* __restrict__ xin, int useBuf) {
    const float* h = useBuf ? g_bufB : xin;
    int w = (blockIdx.x * 256 + threadIdx.x) >> 5;
    int lane = threadIdx.x & 31;
    if (w >= Nn) return;
    float dd = g_dinv[w];
    const float4* h4 = (const float4*)h;
    float4 v = h4[w * 32 + lane];
    float s2 = dd * dd;
    float4 acc = make_float4(v.x*s2, v.y*s2, v.z*s2, v.w*s2);
    int j0 = g_rowptr[w], j1 = g_rowptr[w + 1];
    for (int j = j0; j < j1; j++) {
        int s = __ldg(&g_col[j]);
        float wt = dd * __ldg(&g_cw[j]);
        float4 u = h4[s * 32 + lane];
        acc.x += wt*u.x; acc.y += wt*u.y; acc.z += wt*u.z; acc.w += wt*u.w;
    }
    ((float4*)g_bufA)[w * 32 + lane] = acc;
}

// ---------------- mma.sync bf16-split fused MoE GEMM ----------------
// smem byte offsets
#define SMA_HI  0
#define SMA_LO  32768
#define SMB_HI  65536
#define SMB_LO  98304
#define SM_BIAS 131072                    // 384 floats
#define SM_GATE (131072 + 1536)           // 384 floats
#define SMEM_MM (131072 + 3072)

// swizzled byte offset for [row][k] bf16 tile, 256B rows, 16B-chunk xor swizzle
#define AOFF(row, k) ((row) * 256 + (((((k) >> 3) ^ ((row) & 7))) << 4) + (((k) & 7) << 1))

__device__ __forceinline__ void mma_bf16(float* c, const uint32_t* a, const uint32_t* b) {
    asm volatile("mma.sync.aligned.m16n8k16.row.col.f32.bf16.bf16.f32 "
        "{%0,%1,%2,%3}, {%4,%5,%6,%7}, {%8,%9}, {%0,%1,%2,%3};"
        : "+f"(c[0]), "+f"(c[1]), "+f"(c[2]), "+f"(c[3])
        : "r"(a[0]), "r"(a[1]), "r"(a[2]), "r"(a[3]), "r"(b[0]), "r"(b[1]));
}

__global__ void __launch_bounds__(512) k_gemm_mma(const float* __restrict__ bias3, int layer) {
    extern __shared__ __align__(16) char smc[];
    const int tid = threadIdx.x;
    const int baseM = blockIdx.x * 128;
    const float* gate = layer ? g_gate1 : g_gate0;
    float* bias_s = (float*)(smc + SM_BIAS);
    float* gate_s = (float*)(smc + SM_GATE);

    if (tid < 384) {
        bias_s[tid] = bias3[tid];
        int gi = baseM * 3 + tid;
        gate_s[tid] = (gi < Nn * 3) ? gate[gi] : 0.f;
    }

    // ---- build A tile (bf16 hi/lo, swizzled) ----
    #pragma unroll
    for (int it = 0; it < 4; it++) {
        int idx = it * 512 + tid;          // 0..2047 chunk id
        int row = idx >> 4, kc = idx & 15;
        int grow = baseM + row;
        float4 v0 = make_float4(0.f,0.f,0.f,0.f), v1 = v0;
        if (grow < Nn) {
            const float4* p = (const float4*)(g_bufA + grow * 128 + kc * 8);
            v0 = p[0]; v1 = p[1];
        }
        float f[8] = {v0.x, v0.y, v0.z, v0.w, v1.x, v1.y, v1.z, v1.w};
        __nv_bfloat16 h[8], l[8];
        #pragma unroll
        for (int j = 0; j < 8; j++) {
            h[j] = __float2bfloat16_rn(f[j]);
            l[j] = __float2bfloat16_rn(f[j] - __bfloat162float(h[j]));
        }
        int off = row * 256 + ((kc ^ (row & 7)) << 4);
        *(uint4*)(smc + SMA_HI + off) = *(uint4*)h;
        *(uint4*)(smc + SMA_LO + off) = *(uint4*)l;
    }

    const int lane = tid & 31, wid = tid >> 5;
    const int warpM = wid >> 2, warpN = wid & 3;   // 4x4 warps, each m32 x n32
    const int g = lane >> 2, t4 = lane & 3;

    float out[2][4][4];
    #pragma unroll
    for (int mt = 0; mt < 2; mt++)
        #pragma unroll
        for (int nt = 0; nt < 4; nt++)
            #pragma unroll
            for (int j = 0; j < 4; j++) out[mt][nt][j] = 0.f;

    #pragma unroll 1
    for (int e = 0; e < 3; e++) {
        __syncthreads();   // A/gate ready (e=0); B reuse safe (e>0)
        // ---- load expert B tile (hi/lo) ----
        {
            const uint4* bh = (const uint4*)(g_Wh + (layer * 3 + e) * 16384);
            const uint4* bl = (const uint4*)(g_Wl + (layer * 3 + e) * 16384);
            #pragma unroll
            for (int it = 0; it < 4; it++) {
                int idx = it * 512 + tid;
                int n = idx >> 4, kc = idx & 15;
                int off = n * 256 + ((kc ^ (n & 7)) << 4);
                *(uint4*)(smc + SMB_HI + off) = bh[idx];
                *(uint4*)(smc + SMB_LO + off) = bl[idx];
            }
        }
        __syncthreads();

        float acc[2][4][4];
        #pragma unroll
        for (int mt = 0; mt < 2; mt++)
            #pragma unroll
            for (int nt = 0; nt < 4; nt++)
                #pragma unroll
                for (int j = 0; j < 4; j++) acc[mt][nt][j] = 0.f;

        #pragma unroll
        for (int ks = 0; ks < 8; ks++) {
            #pragma unroll
            for (int p = 0; p < 3; p++) {
                const int ab = (p == 1) ? SMA_LO : SMA_HI;
                const int bb = (p == 2) ? SMB_LO : SMB_HI;
                const int c0 = ks * 16 + t4 * 2;
                uint32_t af[2][4], bfr[4][2];
                #pragma unroll
                for (int mt = 0; mt < 2; mt++) {
                    int r0 = warpM * 32 + mt * 16 + g;
                    af[mt][0] = *(const uint32_t*)(smc + ab + AOFF(r0,     c0));
                    af[mt][1] = *(const uint32_t*)(smc + ab + AOFF(r0 + 8, c0));
                    af[mt][2] = *(const uint32_t*)(smc + ab + AOFF(r0,     c0 + 8));
                    af[mt][3] = *(const uint32_t*)(smc + ab + AOFF(r0 + 8, c0 + 8));
                }
                #pragma unroll
                for (int nt = 0; nt < 4; nt++) {
                    int n0 = warpN * 32 + nt * 8 + g;
                    bfr[nt][0] = *(const uint32_t*)(smc + bb + AOFF(n0, c0));
                    bfr[nt][1] = *(const uint32_t*)(smc + bb + AOFF(n0, c0 + 8));
                }
                #pragma unroll
                for (int mt = 0; mt < 2; mt++)
                    #pragma unroll
                    for (int nt = 0; nt < 4; nt++)
                        mma_bf16(acc[mt][nt], af[mt], bfr[nt]);
            }
        }

        // ---- gated relu epilogue ----
        #pragma unroll
        for (int mt = 0; mt < 2; mt++) {
            int rloc = warpM * 32 + mt * 16 + g;
            float g0 = gate_s[rloc * 3 + e];
            float g1 = gate_s[(rloc + 8) * 3 + e];
            #pragma unroll
            for (int nt = 0; nt < 4; nt++) {
                int col = warpN * 32 + nt * 8 + t4 * 2;
                float bb0 = bias_s[e * 128 + col], bb1 = bias_s[e * 128 + col + 1];
                out[mt][nt][0] += g0 * fmaxf(acc[mt][nt][0] + bb0, 0.f);
                out[mt][nt][1] += g0 * fmaxf(acc[mt][nt][1] + bb1, 0.f);
                out[mt][nt][2] += g1 * fmaxf(acc[mt][nt][2] + bb0, 0.f);
                out[mt][nt][3] += g1 * fmaxf(acc[mt][nt][3] + bb1, 0.f);
            }
        }
    }

    // ---- writeback ----
    #pragma unroll
    for (int mt = 0; mt < 2; mt++) {
        int r0 = baseM + warpM * 32 + mt * 16 + g;
        #pragma unroll
        for (int nt = 0; nt < 4; nt++) {
            int col = warpN * 32 + nt * 8 + t4 * 2;
            if (r0 < Nn)
                *(float2*)(g_bufB + r0 * 128 + col) = make_float2(out[mt][nt][0], out[mt][nt][1]);
            if (r0 + 8 < Nn)
                *(float2*)(g_bufB + (r0 + 8) * 128 + col) = make_float2(out[mt][nt][2], out[mt][nt][3]);
        }
    }
}

// ---------------- pooling + final ----------------
__global__ void k_pool(const int* __restrict__ batch) {
    int idx = blockIdx.x * blockDim.x + threadIdx.x;
    if (idx >= Nn * 32) return;
    int n = idx >> 5, c = idx & 31;
    int g = batch[n];
    float4 v = ((const float4*)g_bufB)[n * 32 + c];
    atomicAdd(&g_sums[g * 128 + c * 4 + 0], v.x);
    atomicAdd(&g_sums[g * 128 + c * 4 + 1], v.y);
    atomicAdd(&g_sums[g * 128 + c * 4 + 2], v.z);
    atomicAdd(&g_sums[g * 128 + c * 4 + 3], v.w);
    if (c == 0) atomicAdd(&g_cnt[g], 1.0f);
}

__global__ void k_final(const float* __restrict__ Wf,
                        const float* __restrict__ bf,
                        float* __restrict__ out) {
    __shared__ float p[128];
    int g = blockIdx.x;
    float inv = 1.0f / fmaxf(g_cnt[g], 1.0f);
    if (threadIdx.x < 128) p[threadIdx.x] = g_sums[g * 128 + threadIdx.x] * inv;
    __syncthreads();
    if (threadIdx.x < OUTC) {
        float acc = bf[threadIdx.x];
        #pragma unroll 16
        for (int k = 0; k < 128; k++)
            acc += p[k] * Wf[k * OUTC + threadIdx.x];
        out[g * OUTC + threadIdx.x] = acc;
    }
}

// ---------------- launch ----------------
extern "C" void kernel_launch(void* const* d_in, const int* in_sizes, int n_in,
                              void* d_out, int out_size) {
    const float* x     = (const float*)d_in[0];
    const float* top   = (const float*)d_in[1];
    const int*   ei    = (const int*)d_in[2];
    const int*   batch = (const int*)d_in[3];
    const float* W0    = (const float*)d_in[4];
    const float* b0    = (const float*)d_in[5];
    const float* Wg0   = (const float*)d_in[6];
    const float* W1    = (const float*)d_in[7];
    const float* b1    = (const float*)d_in[8];
    const float* Wg1   = (const float*)d_in[9];
    const float* Wf    = (const float*)d_in[10];
    const float* bf    = (const float*)d_in[11];
    float*       out   = (float*)d_out;

    cudaFuncSetAttribute(k_gemm_mma, cudaFuncAttributeMaxDynamicSharedMemorySize, SMEM_MM);

    k_zero<<<(Nn + 255) / 256, 256>>>();
    k_hist<<<(Ee + 255) / 256, 256>>>(ei);
    k_prep<<<(Nn + 255) / 256, 256>>>(top, Wg0, Wg1);
    k_wprep<<<(2 * 3 * 16384 + 255) / 256, 256>>>(W0, W1);
    k_scan1<<<98, 512>>>();
    k_scan2<<<1, 128>>>();
    k_scan3<<<(Nn + 255) / 256, 256>>>();
    k_fill<<<(Ee + 255) / 256, 256>>>(ei);

    const int gemmGrid = (Nn + 127) / 128;   // 391
    // layer 0
    k_agg<<<(Nn * 32 + 255) / 256, 256>>>(x, 0);
    k_gemm_mma<<<gemmGrid, 512, SMEM_MM>>>(b0, 0);
    // layer 1
    k_agg<<<(Nn * 32 + 255) / 256, 256>>>(x, 1);
    k_gemm_mma<<<gemmGrid, 512, SMEM_MM>>>(b1, 1);

    k_pool<<<(Nn * 32 + 255) / 256, 256>>>(batch);
    k_final<<<NG, 128>>>(Wf, bf, out);
}

// round 5
// speedup vs baseline: 2.5048x; 1.6992x over previous
#include <cuda_runtime.h>
#include <cuda_bf16.h>
#include <cstdint>

#define Nn   50000
#define Ee   800000
#define HID  128
#define OUTC 64
#define NG   64
#define TEMP_INV (1.0f/101.0f)

// ---------------- scratch ----------------
static __device__ int    g_deg[Nn];
static __device__ float  g_dinv[Nn];
static __device__ int    g_rowptr[Nn + 1];
static __device__ int    g_cursor[Nn];
static __device__ __align__(8) int2 g_edge[Ee];     // (src, dinv[src] bits)
static __device__ float  g_gate0[Nn * 3];
static __device__ float  g_gate1[Nn * 3];
static __device__ float  g_bufA[Nn * HID];
static __device__ float  g_bufB[Nn * HID];
static __device__ float  g_sums[NG * HID];
static __device__ float  g_cnt[NG];
static __device__ int    g_tmpScan[Nn];
static __device__ int    g_blockSums[128];
static __device__ int    g_blockOffs[128];
// bf16 split transposed weights: [L][e][n][k], hi and lo
static __device__ __align__(16) __nv_bfloat16 g_Wh[2 * 3 * 128 * 128];
static __device__ __align__(16) __nv_bfloat16 g_Wl[2 * 3 * 128 * 128];

__device__ __forceinline__ uint32_t smem_u32(const void* p) {
    uint32_t a;
    asm("{ .reg .u64 t; cvta.to.shared.u64 t, %1; cvt.u32.u64 %0, t; }" : "=r"(a) : "l"(p));
    return a;
}

// ---------------- prep kernels ----------------
__global__ void k_zero() {
    int i = blockIdx.x * blockDim.x + threadIdx.x;
    if (i < Nn) { g_deg[i] = 0; g_cursor[i] = 0; }
    if (i < NG * HID) g_sums[i] = 0.f;
    if (i < NG) g_cnt[i] = 0.f;
}

__global__ void k_hist(const int* __restrict__ ei) {
    int i = blockIdx.x * blockDim.x + threadIdx.x;
    if (i < Ee) atomicAdd(&g_deg[ei[Ee + i]], 1);
}

__global__ void k_prep(const float* __restrict__ top,
                       const float* __restrict__ Wg0,
                       const float* __restrict__ Wg1) {
    int n = blockIdx.x * blockDim.x + threadIdx.x;
    if (n >= Nn) return;
    g_dinv[n] = rsqrtf((float)(g_deg[n] + 1));
    float t0 = top[n*4+0], t1 = top[n*4+1], t2 = top[n*4+2], t3 = top[n*4+3];
    #pragma unroll
    for (int L = 0; L < 2; L++) {
        const float* Wg = L ? Wg1 : Wg0;
        float* gate = L ? g_gate1 : g_gate0;
        float l[3];
        #pragma unroll
        for (int e = 0; e < 3; e++)
            l[e] = (t0*Wg[e*4+0] + t1*Wg[e*4+1] + t2*Wg[e*4+2] + t3*Wg[e*4+3]) * TEMP_INV;
        float mx = fmaxf(l[0], fmaxf(l[1], l[2]));
        float e0 = expf(l[0]-mx), e1 = expf(l[1]-mx), e2 = expf(l[2]-mx);
        float inv = 1.0f / (e0 + e1 + e2);
        gate[n*3+0] = e0*inv; gate[n*3+1] = e1*inv; gate[n*3+2] = e2*inv;
    }
}

// transpose + bf16-split expert weights: [L][e][n][k] from W[e][k][n]
__global__ void k_wprep(const float* __restrict__ W0, const float* __restrict__ W1) {
    int idx = blockIdx.x * blockDim.x + threadIdx.x;
    if (idx >= 2 * 3 * 16384) return;
    int L = idx / 49152, rem = idx % 49152;
    int e = rem / 16384, nk = rem % 16384;
    int n = nk >> 7, k = nk & 127;
    const float* W = L ? W1 : W0;
    float w = W[e * 16384 + k * 128 + n];
    __nv_bfloat16 hi = __float2bfloat16_rn(w);
    g_Wh[idx] = hi;
    g_Wl[idx] = __float2bfloat16_rn(w - __bfloat162float(hi));
}

// ---------------- scan ----------------
__global__ void k_scan1() {
    __shared__ int s[512];
    int i = blockIdx.x * 512 + threadIdx.x;
    int v = (i < Nn) ? g_deg[i] : 0;
    s[threadIdx.x] = v; __syncthreads();
    for (int off = 1; off < 512; off <<= 1) {
        int t = (threadIdx.x >= off) ? s[threadIdx.x - off] : 0;
        __syncthreads(); s[threadIdx.x] += t; __syncthreads();
    }
    if (i < Nn) g_tmpScan[i] = s[threadIdx.x];
    if (threadIdx.x == 511) g_blockSums[blockIdx.x] = s[511];
}
__global__ void k_scan2() {
    __shared__ int s[128];
    int t = threadIdx.x;
    int v = (t < 98) ? g_blockSums[t] : 0;
    s[t] = v; __syncthreads();
    for (int off = 1; off < 128; off <<= 1) {
        int u = (t >= off) ? s[t - off] : 0;
        __syncthreads(); s[t] += u; __syncthreads();
    }
    if (t < 98) g_blockOffs[t] = s[t] - v;
}
__global__ void k_scan3() {
    int i = blockIdx.x * blockDim.x + threadIdx.x;
    if (i == 0) g_rowptr[0] = 0;
    if (i < Nn) g_rowptr[i + 1] = g_tmpScan[i] + g_blockOffs[i >> 9];
}
__global__ void k_fill(const int* __restrict__ ei) {
    int i = blockIdx.x * blockDim.x + threadIdx.x;
    if (i >= Ee) return;
    int s = ei[i], d = ei[Ee + i];
    int p = g_rowptr[d] + atomicAdd(&g_cursor[d], 1);
    g_edge[p] = make_int2(s, __float_as_int(g_dinv[s]));
}

// ---------------- CSR aggregation ----------------
__global__ void __launch_bounds__(256) k_agg(const float* __restrict__ xin, int useBuf) {
    const float* h = useBuf ? g_bufB : xin;
    int w = (blockIdx.x * 256 + threadIdx.x) >> 5;
    int lane = threadIdx.x & 31;
    if (w >= Nn) return;
    float dd = g_dinv[w];
    const float4* h4 = (const float4*)h;
    float4 v = h4[w * 32 + lane];
    float s2 = dd * dd;
    float4 acc = make_float4(v.x*s2, v.y*s2, v.z*s2, v.w*s2);
    int j0 = g_rowptr[w], j1 = g_rowptr[w + 1];
    #pragma unroll 2
    for (int j = j0; j < j1; j++) {
        int2 ed = __ldg(&g_edge[j]);
        float wt = dd * __int_as_float(ed.y);
        float4 u = h4[ed.x * 32 + lane];
        acc.x += wt*u.x; acc.y += wt*u.y; acc.z += wt*u.z; acc.w += wt*u.w;
    }
    ((float4*)g_bufA)[w * 32 + lane] = acc;
}

// ---------------- mma.sync bf16-split fused MoE GEMM (cp.async pipelined) ----------------
// smem byte offsets
#define SMA_HI  0
#define SMA_LO  32768
#define SMB0    65536                     // stage0: hi 32KB + lo 32KB
#define SMB1    131072                    // stage1
#define SM_BIAS 196608                    // 384 floats
#define SM_GATE (196608 + 1536)           // 384 floats
#define SMEM_MM (196608 + 3072)

// swizzled byte offset for [row][k] bf16 tile, 256B rows, 16B-chunk xor swizzle
#define AOFF(row, k) ((row) * 256 + (((((k) >> 3) ^ ((row) & 7))) << 4) + (((k) & 7) << 1))

__device__ __forceinline__ void mma_bf16(float* c, const uint32_t* a, const uint32_t* b) {
    asm volatile("mma.sync.aligned.m16n8k16.row.col.f32.bf16.bf16.f32 "
        "{%0,%1,%2,%3}, {%4,%5,%6,%7}, {%8,%9}, {%0,%1,%2,%3};"
        : "+f"(c[0]), "+f"(c[1]), "+f"(c[2]), "+f"(c[3])
        : "r"(a[0]), "r"(a[1]), "r"(a[2]), "r"(a[3]), "r"(b[0]), "r"(b[1]));
}

__device__ __forceinline__ void cp16(uint32_t dst, const void* src) {
    asm volatile("cp.async.cg.shared.global [%0], [%1], 16;" :: "r"(dst), "l"(src));
}

// issue expert-e B tile (hi+lo) into stage buffer
__device__ __forceinline__ void issueB(char* smc, uint32_t smb, int stagebase,
                                       int layer, int e, int tid) {
    const uint4* bh = (const uint4*)(g_Wh + (layer * 3 + e) * 16384);
    const uint4* bl = (const uint4*)(g_Wl + (layer * 3 + e) * 16384);
    #pragma unroll
    for (int it = 0; it < 4; it++) {
        int idx = it * 512 + tid;
        int n = idx >> 4, kc = idx & 15;
        int off = n * 256 + ((kc ^ (n & 7)) << 4);
        cp16(smb + stagebase + off,         bh + idx);
        cp16(smb + stagebase + 32768 + off, bl + idx);
    }
    asm volatile("cp.async.commit_group;");
}

__global__ void __launch_bounds__(512) k_gemm_mma(const float* __restrict__ bias3, int layer) {
    extern __shared__ __align__(16) char smc[];
    const uint32_t smb = smem_u32(smc);
    const int tid = threadIdx.x;
    const int baseM = blockIdx.x * 128;
    const float* gate = layer ? g_gate1 : g_gate0;
    float* bias_s = (float*)(smc + SM_BIAS);
    float* gate_s = (float*)(smc + SM_GATE);

    // prefetch expert 0 B tile first (overlaps with A build)
    issueB(smc, smb, SMB0, layer, 0, tid);

    if (tid < 384) {
        bias_s[tid] = bias3[tid];
        int gi = baseM * 3 + tid;
        gate_s[tid] = (gi < Nn * 3) ? gate[gi] : 0.f;
    }

    // ---- build A tile (bf16 hi/lo, swizzled) ----
    #pragma unroll
    for (int it = 0; it < 4; it++) {
        int idx = it * 512 + tid;          // 0..2047 chunk id
        int row = idx >> 4, kc = idx & 15;
        int grow = baseM + row;
        float4 v0 = make_float4(0.f,0.f,0.f,0.f), v1 = v0;
        if (grow < Nn) {
            const float4* p = (const float4*)(g_bufA + grow * 128 + kc * 8);
            v0 = p[0]; v1 = p[1];
        }
        float f[8] = {v0.x, v0.y, v0.z, v0.w, v1.x, v1.y, v1.z, v1.w};
        __nv_bfloat16 h[8], l[8];
        #pragma unroll
        for (int j = 0; j < 8; j++) {
            h[j] = __float2bfloat16_rn(f[j]);
            l[j] = __float2bfloat16_rn(f[j] - __bfloat162float(h[j]));
        }
        int off = row * 256 + ((kc ^ (row & 7)) << 4);
        *(uint4*)(smc + SMA_HI + off) = *(uint4*)h;
        *(uint4*)(smc + SMA_LO + off) = *(uint4*)l;
    }

    const int lane = tid & 31, wid = tid >> 5;
    const int warpM = wid >> 2, warpN = wid & 3;   // 4x4 warps, each m32 x n32
    const int g = lane >> 2, t4 = lane & 3;

    float out[2][4][4];
    #pragma unroll
    for (int mt = 0; mt < 2; mt++)
        #pragma unroll
        for (int nt = 0; nt < 4; nt++)
            #pragma unroll
            for (int j = 0; j < 4; j++) out[mt][nt][j] = 0.f;

    #pragma unroll 1
    for (int e = 0; e < 3; e++) {
        __syncthreads();   // prev compute done (stage reuse safe); A stores done (e=0)
        if (e < 2) issueB(smc, smb, (e & 1) ? SMB0 : SMB1, layer, e + 1, tid);
        if (e < 2) { asm volatile("cp.async.wait_group 1;"); }
        else       { asm volatile("cp.async.wait_group 0;"); }
        __syncthreads();   // B(e) visible to all warps

        const int sb  = (e & 1) ? SMB1 : SMB0;
        const int sbl = sb + 32768;

        float acc[2][4][4];
        #pragma unroll
        for (int mt = 0; mt < 2; mt++)
            #pragma unroll
            for (int nt = 0; nt < 4; nt++)
                #pragma unroll
                for (int j = 0; j < 4; j++) acc[mt][nt][j] = 0.f;

        #pragma unroll
        for (int ks = 0; ks < 8; ks++) {
            const int c0 = ks * 16 + t4 * 2;
            uint32_t afh[2][4], afl[2][4], bfh[4][2], bfl[4][2];
            #pragma unroll
            for (int mt = 0; mt < 2; mt++) {
                int r0 = warpM * 32 + mt * 16 + g;
                afh[mt][0] = *(const uint32_t*)(smc + SMA_HI + AOFF(r0,     c0));
                afh[mt][1] = *(const uint32_t*)(smc + SMA_HI + AOFF(r0 + 8, c0));
                afh[mt][2] = *(const uint32_t*)(smc + SMA_HI + AOFF(r0,     c0 + 8));
                afh[mt][3] = *(const uint32_t*)(smc + SMA_HI + AOFF(r0 + 8, c0 + 8));
                afl[mt][0] = *(const uint32_t*)(smc + SMA_LO + AOFF(r0,     c0));
                afl[mt][1] = *(const uint32_t*)(smc + SMA_LO + AOFF(r0 + 8, c0));
                afl[mt][2] = *(const uint32_t*)(smc + SMA_LO + AOFF(r0,     c0 + 8));
                afl[mt][3] = *(const uint32_t*)(smc + SMA_LO + AOFF(r0 + 8, c0 + 8));
            }
            #pragma unroll
            for (int nt = 0; nt < 4; nt++) {
                int n0 = warpN * 32 + nt * 8 + g;
                bfh[nt][0] = *(const uint32_t*)(smc + sb  + AOFF(n0, c0));
                bfh[nt][1] = *(const uint32_t*)(smc + sb  + AOFF(n0, c0 + 8));
                bfl[nt][0] = *(const uint32_t*)(smc + sbl + AOFF(n0, c0));
                bfl[nt][1] = *(const uint32_t*)(smc + sbl + AOFF(n0, c0 + 8));
            }
            #pragma unroll
            for (int mt = 0; mt < 2; mt++)
                #pragma unroll
                for (int nt = 0; nt < 4; nt++) {
                    mma_bf16(acc[mt][nt], afh[mt], bfh[nt]);
                    mma_bf16(acc[mt][nt], afl[mt], bfh[nt]);
                    mma_bf16(acc[mt][nt], afh[mt], bfl[nt]);
                }
        }

        // ---- gated relu epilogue ----
        #pragma unroll
        for (int mt = 0; mt < 2; mt++) {
            int rloc = warpM * 32 + mt * 16 + g;
            float g0 = gate_s[rloc * 3 + e];
            float g1 = gate_s[(rloc + 8) * 3 + e];
            #pragma unroll
            for (int nt = 0; nt < 4; nt++) {
                int col = warpN * 32 + nt * 8 + t4 * 2;
                float bb0 = bias_s[e * 128 + col], bb1 = bias_s[e * 128 + col + 1];
                out[mt][nt][0] += g0 * fmaxf(acc[mt][nt][0] + bb0, 0.f);
                out[mt][nt][1] += g0 * fmaxf(acc[mt][nt][1] + bb1, 0.f);
                out[mt][nt][2] += g1 * fmaxf(acc[mt][nt][2] + bb0, 0.f);
                out[mt][nt][3] += g1 * fmaxf(acc[mt][nt][3] + bb1, 0.f);
            }
        }
    }

    // ---- writeback ----
    #pragma unroll
    for (int mt = 0; mt < 2; mt++) {
        int r0 = baseM + warpM * 32 + mt * 16 + g;
        #pragma unroll
        for (int nt = 0; nt < 4; nt++) {
            int col = warpN * 32 + nt * 8 + t4 * 2;
            if (r0 < Nn)
                *(float2*)(g_bufB + r0 * 128 + col) = make_float2(out[mt][nt][0], out[mt][nt][1]);
            if (r0 + 8 < Nn)
                *(float2*)(g_bufB + (r0 + 8) * 128 + col) = make_float2(out[mt][nt][2], out[mt][nt][3]);
        }
    }
}

// ---------------- segment-aware pooling + final ----------------
__global__ void __launch_bounds__(256) k_pool(const int* __restrict__ batch) {
    int tid = threadIdx.x;
    int c4 = tid & 31;
    int nb = blockIdx.x * 64 + (tid >> 5) * 8;
    if (nb >= Nn) return;
    float4 acc = make_float4(0.f, 0.f, 0.f, 0.f);
    float cnt = 0.f;
    int curg = batch[nb];
    #pragma unroll
    for (int k = 0; k < 8; k++) {
        int n = nb + k;
        if (n >= Nn) break;
        int gg = batch[n];
        if (gg != curg) {
            atomicAdd(&g_sums[curg * 128 + c4 * 4 + 0], acc.x);
            atomicAdd(&g_sums[curg * 128 + c4 * 4 + 1], acc.y);
            atomicAdd(&g_sums[curg * 128 + c4 * 4 + 2], acc.z);
            atomicAdd(&g_sums[curg * 128 + c4 * 4 + 3], acc.w);
            if (c4 == 0) atomicAdd(&g_cnt[curg], cnt);
            acc = make_float4(0.f, 0.f, 0.f, 0.f); cnt = 0.f; curg = gg;
        }
        float4 v = ((const float4*)g_bufB)[n * 32 + c4];
        acc.x += v.x; acc.y += v.y; acc.z += v.z; acc.w += v.w;
        cnt += 1.f;
    }
    atomicAdd(&g_sums[curg * 128 + c4 * 4 + 0], acc.x);
    atomicAdd(&g_sums[curg * 128 + c4 * 4 + 1], acc.y);
    atomicAdd(&g_sums[curg * 128 + c4 * 4 + 2], acc.z);
    atomicAdd(&g_sums[curg * 128 + c4 * 4 + 3], acc.w);
    if (c4 == 0) atomicAdd(&g_cnt[curg], cnt);
}

__global__ void k_final(const float* __restrict__ Wf,
                        const float* __restrict__ bf,
                        float* __restrict__ out) {
    __shared__ float p[128];
    int g = blockIdx.x;
    float inv = 1.0f / fmaxf(g_cnt[g], 1.0f);
    if (threadIdx.x < 128) p[threadIdx.x] = g_sums[g * 128 + threadIdx.x] * inv;
    __syncthreads();
    if (threadIdx.x < OUTC) {
        float acc = bf[threadIdx.x];
        #pragma unroll 16
        for (int k = 0; k < 128; k++)
            acc += p[k] * Wf[k * OUTC + threadIdx.x];
        out[g * OUTC + threadIdx.x] = acc;
    }
}

// ---------------- launch ----------------
extern "C" void kernel_launch(void* const* d_in, const int* in_sizes, int n_in,
                              void* d_out, int out_size) {
    const float* x     = (const float*)d_in[0];
    const float* top   = (const float*)d_in[1];
    const int*   ei    = (const int*)d_in[2];
    const int*   batch = (const int*)d_in[3];
    const float* W0    = (const float*)d_in[4];
    const float* b0    = (const float*)d_in[5];
    const float* Wg0   = (const float*)d_in[6];
    const float* W1    = (const float*)d_in[7];
    const float* b1    = (const float*)d_in[8];
    const float* Wg1   = (const float*)d_in[9];
    const float* Wf    = (const float*)d_in[10];
    const float* bf    = (const float*)d_in[11];
    float*       out   = (float*)d_out;

    cudaFuncSetAttribute(k_gemm_mma, cudaFuncAttributeMaxDynamicSharedMemorySize, SMEM_MM);

    k_zero<<<(Nn + 255) / 256, 256>>>();
    k_hist<<<(Ee + 255) / 256, 256>>>(ei);
    k_prep<<<(Nn + 255) / 256, 256>>>(top, Wg0, Wg1);
    k_wprep<<<(2 * 3 * 16384 + 255) / 256, 256>>>(W0, W1);
    k_scan1<<<98, 512>>>();
    k_scan2<<<1, 128>>>();
    k_scan3<<<(Nn + 255) / 256, 256>>>();
    k_fill<<<(Ee + 255) / 256, 256>>>(ei);

    const int gemmGrid = (Nn + 127) / 128;   // 391
    // layer 0
    k_agg<<<(Nn * 32 + 255) / 256, 256>>>(x, 0);
    k_gemm_mma<<<gemmGrid, 512, SMEM_MM>>>(b0, 0);
    // layer 1
    k_agg<<<(Nn * 32 + 255) / 256, 256>>>(x, 1);
    k_gemm_mma<<<gemmGrid, 512, SMEM_MM>>>(b1, 1);

    k_pool<<<(Nn + 63) / 64, 256>>>(batch);
    k_final<<<NG, 128>>>(Wf, bf, out);
}